// round 1
// baseline (speedup 1.0000x reference)
#include <cuda_runtime.h>
#include <cstdint>
#include <cstddef>

// VeRA: y = x @ W^T + ((x @ A^T) * d) @ B^T + b
// x: [8192, 4096] f32, W: [4096, 4096], A: [256, 4096], B: [4096, 256], d: [256], b: [4096]
// All K-major (row-major with contiguous K) -> mma row.col form fits directly.

#define M_TOT 8192
#define N_TOT 4096
#define K_TOT 4096
#define RNK   256

#define BM 128
#define BN 128
#define BK 32
#define PITCH 36               // 32 + 4 floats padding: conflict-free frag loads, 16B-aligned rows
#define SBUF (128 * PITCH)     // floats per buffer per operand

// Scratch for xa = (x @ A^T) * d   (8 MB, module-static: allowed)
__device__ float g_xa[(size_t)M_TOT * RNK];

__device__ __forceinline__ uint32_t f2tf(float f) {
    uint32_t r;
    asm("cvt.rna.tf32.f32 %0, %1;" : "=r"(r) : "f"(f));
    return r;
}

__device__ __forceinline__ void cp16(float* s, const float* g) {
    uint32_t sa = (uint32_t)__cvta_generic_to_shared(s);
    asm volatile("cp.async.cg.shared.global [%0], [%1], 16;" :: "r"(sa), "l"(g));
}

__device__ __forceinline__ void mma8(float* c, const uint32_t* a, const uint32_t* b) {
    asm volatile(
        "mma.sync.aligned.m16n8k8.row.col.f32.tf32.tf32.f32 "
        "{%0,%1,%2,%3}, {%4,%5,%6,%7}, {%8,%9}, {%0,%1,%2,%3};"
        : "+f"(c[0]), "+f"(c[1]), "+f"(c[2]), "+f"(c[3])
        : "r"(a[0]), "r"(a[1]), "r"(a[2]), "r"(a[3]), "r"(b[0]), "r"(b[1]));
}

// Accumulate C[128x128] += Ag[m_block:+128, 0:K] * Bg[n_block:+128, 0:K]^T
// Ag is [*, lda] row-major, Bg is [*, ldb] row-major (K contiguous in both).
// Double-buffered cp.async pipeline, BK=32 per stage.
__device__ __forceinline__ void gemm_accum(
    const float* __restrict__ Ag, int lda,
    const float* __restrict__ Bg, int ldb,
    int K, float (&acc)[4][4][4],
    float* sA, float* sB,
    int m_block, int n_block, int tid)
{
    const int lane = tid & 31;
    const int warp = tid >> 5;
    const int wm = warp & 1;      // 2 warps along M (64 rows each)
    const int wn = warp >> 1;     // 4 warps along N (32 cols each)
    const int lr = lane >> 2;     // 0..7
    const int lc = lane & 3;      // 0..3
    const int ldr = tid >> 3;     // 0..31 (loader row within group of 32)
    const int ldc = (tid & 7) * 4;// loader col (float4 granule)

    const int nk = K / BK;

    auto issue = [&](int kt, int buf) {
        const float* ga = Ag + (size_t)m_block * lda + kt * BK + ldc;
        const float* gb = Bg + (size_t)n_block * ldb + kt * BK + ldc;
        float* sa = sA + buf * SBUF;
        float* sb = sB + buf * SBUF;
        #pragma unroll
        for (int i = 0; i < 4; i++) {
            int row = ldr + i * 32;
            cp16(sa + row * PITCH + ldc, ga + (size_t)row * lda);
            cp16(sb + row * PITCH + ldc, gb + (size_t)row * ldb);
        }
        asm volatile("cp.async.commit_group;" ::: "memory");
    };

    issue(0, 0);
    asm volatile("cp.async.wait_group 0;" ::: "memory");
    __syncthreads();

    for (int kt = 0; kt < nk; kt++) {
        const int buf = kt & 1;
        if (kt + 1 < nk) issue(kt + 1, buf ^ 1);

        const float* sa = sA + buf * SBUF;
        const float* sb = sB + buf * SBUF;

        #pragma unroll
        for (int k8 = 0; k8 < 4; k8++) {
            uint32_t af[4][4];
            uint32_t bf[4][2];
            #pragma unroll
            for (int mi = 0; mi < 4; mi++) {
                const float* p = sa + (wm * 64 + mi * 16 + lr) * PITCH + k8 * 8 + lc;
                af[mi][0] = f2tf(p[0]);
                af[mi][1] = f2tf(p[8 * PITCH]);
                af[mi][2] = f2tf(p[4]);
                af[mi][3] = f2tf(p[8 * PITCH + 4]);
            }
            #pragma unroll
            for (int ni = 0; ni < 4; ni++) {
                const float* p = sb + (wn * 32 + ni * 8 + lr) * PITCH + k8 * 8 + lc;
                bf[ni][0] = f2tf(p[0]);
                bf[ni][1] = f2tf(p[4]);
            }
            #pragma unroll
            for (int mi = 0; mi < 4; mi++)
                #pragma unroll
                for (int ni = 0; ni < 4; ni++)
                    mma8(acc[mi][ni], af[mi], bf[ni]);
        }

        if (kt + 1 < nk) {
            asm volatile("cp.async.wait_group 0;" ::: "memory");
            __syncthreads();
        }
    }
    __syncthreads();  // smem may be reused by a second phase
}

// Kernel A: g_xa = (x @ A^T) * d    [8192, 256]
__global__ __launch_bounds__(256) void vera_xa_kernel(
    const float* __restrict__ x, const float* __restrict__ Amat,
    const float* __restrict__ dvec)
{
    extern __shared__ float smem[];
    float* sA = smem;
    float* sB = smem + 2 * SBUF;

    float acc[4][4][4];
    #pragma unroll
    for (int i = 0; i < 4; i++)
        #pragma unroll
        for (int j = 0; j < 4; j++)
            #pragma unroll
            for (int k = 0; k < 4; k++) acc[i][j][k] = 0.0f;

    const int m_block = blockIdx.y * BM;
    const int n_block = blockIdx.x * BN;
    const int tid = threadIdx.x;

    gemm_accum(x, K_TOT, Amat, K_TOT, K_TOT, acc, sA, sB, m_block, n_block, tid);

    const int lane = tid & 31;
    const int warp = tid >> 5;
    const int wm = warp & 1, wn = warp >> 1;
    const int lr = lane >> 2, lc = lane & 3;

    #pragma unroll
    for (int mi = 0; mi < 4; mi++) {
        #pragma unroll
        for (int ni = 0; ni < 4; ni++) {
            const int m = m_block + wm * 64 + mi * 16 + lr;
            const int n = n_block + wn * 32 + ni * 8 + lc * 2;
            const float d0 = dvec[n], d1 = dvec[n + 1];
            float2 v0 = make_float2(acc[mi][ni][0] * d0, acc[mi][ni][1] * d1);
            float2 v1 = make_float2(acc[mi][ni][2] * d0, acc[mi][ni][3] * d1);
            *(float2*)&g_xa[(size_t)m * RNK + n]       = v0;
            *(float2*)&g_xa[(size_t)(m + 8) * RNK + n] = v1;
        }
    }
}

// Kernel B: out = x @ W^T + g_xa @ B^T + b    [8192, 4096]
__global__ __launch_bounds__(256) void vera_main_kernel(
    const float* __restrict__ x, const float* __restrict__ W,
    const float* __restrict__ Bmat, const float* __restrict__ bias,
    float* __restrict__ out)
{
    extern __shared__ float smem[];
    float* sA = smem;
    float* sB = smem + 2 * SBUF;

    float acc[4][4][4];
    #pragma unroll
    for (int i = 0; i < 4; i++)
        #pragma unroll
        for (int j = 0; j < 4; j++)
            #pragma unroll
            for (int k = 0; k < 4; k++) acc[i][j][k] = 0.0f;

    const int m_block = blockIdx.y * BM;
    const int n_block = blockIdx.x * BN;
    const int tid = threadIdx.x;

    // Phase 1: x @ W^T (K = 4096)
    gemm_accum(x, K_TOT, W, K_TOT, K_TOT, acc, sA, sB, m_block, n_block, tid);
    // Phase 2: xa @ B^T (K = 256)
    gemm_accum(g_xa, RNK, Bmat, RNK, RNK, acc, sA, sB, m_block, n_block, tid);

    const int lane = tid & 31;
    const int warp = tid >> 5;
    const int wm = warp & 1, wn = warp >> 1;
    const int lr = lane >> 2, lc = lane & 3;

    #pragma unroll
    for (int mi = 0; mi < 4; mi++) {
        #pragma unroll
        for (int ni = 0; ni < 4; ni++) {
            const int m = m_block + wm * 64 + mi * 16 + lr;
            const int n = n_block + wn * 32 + ni * 8 + lc * 2;
            const float b0 = bias[n], b1 = bias[n + 1];
            float2 v0 = make_float2(acc[mi][ni][0] + b0, acc[mi][ni][1] + b1);
            float2 v1 = make_float2(acc[mi][ni][2] + b0, acc[mi][ni][3] + b1);
            *(float2*)&out[(size_t)m * N_TOT + n]       = v0;
            *(float2*)&out[(size_t)(m + 8) * N_TOT + n] = v1;
        }
    }
}

extern "C" void kernel_launch(void* const* d_in, const int* in_sizes, int n_in,
                              void* d_out, int out_size)
{
    const float* x    = (const float*)d_in[0];
    const float* W    = (const float*)d_in[1];
    const float* Amat = (const float*)d_in[2];
    const float* Bmat = (const float*)d_in[3];
    const float* dvec = (const float*)d_in[4];
    const float* bias = (const float*)d_in[5];
    float* out = (float*)d_out;

    const int smem_bytes = 4 * SBUF * sizeof(float);  // 73728 B
    cudaFuncSetAttribute(vera_xa_kernel,   cudaFuncAttributeMaxDynamicSharedMemorySize, smem_bytes);
    cudaFuncSetAttribute(vera_main_kernel, cudaFuncAttributeMaxDynamicSharedMemorySize, smem_bytes);

    vera_xa_kernel<<<dim3(RNK / BN, M_TOT / BM), 256, smem_bytes>>>(x, Amat, dvec);
    vera_main_kernel<<<dim3(N_TOT / BN, M_TOT / BM), 256, smem_bytes>>>(x, W, Bmat, bias, out);
}

// round 5
// speedup vs baseline: 1.3673x; 1.3673x over previous
#include <cuda_runtime.h>
#include <cstdint>
#include <cstddef>

// VeRA: y = x @ W^T + ((x @ A^T) * d) @ B^T + b    (all f32)
// x:[8192,4096] W:[4096,4096] A:[256,4096] B:[4096,256] d:[256] b:[4096]
// Path: prepass RNA-round to tf32 -> mma.sync m16n8k8 tf32 with ldmatrix fragments.

#define M_TOT 8192
#define N_TOT 4096
#define K_TOT 4096
#define RNK   256

#define BM 256
#define BN 128
#define BK 32
#define STAGES 4
#define A_BYTES (BM * 128)            // 32768
#define B_BYTES (BN * 128)            // 16384
#define STAGE_BYTES (A_BYTES + B_BYTES)   // 49152
#define SMEM_TOTAL (STAGES * STAGE_BYTES) // 196608

// ---------- static scratch ----------
__device__ float g_xr[(size_t)M_TOT * K_TOT];   // tf32-rounded x
__device__ float g_wr[(size_t)N_TOT * K_TOT];   // tf32-rounded W
__device__ float g_ar[(size_t)RNK * K_TOT];     // tf32-rounded A
__device__ float g_br[(size_t)N_TOT * RNK];     // tf32-rounded B
__device__ float g_xa[(size_t)M_TOT * RNK];     // xa = (x@A^T)*d, tf32-rounded

// ---------- helpers ----------
__device__ __forceinline__ uint32_t f2tf(float f) {
    uint32_t r; asm("cvt.rna.tf32.f32 %0, %1;" : "=r"(r) : "f"(f)); return r;
}
__device__ __forceinline__ uint32_t smem_u32(const void* p) {
    uint32_t a;
    asm("{ .reg .u64 t; cvta.to.shared.u64 t, %1; cvt.u32.u64 %0, t; }" : "=r"(a) : "l"(p));
    return a;
}
__device__ __forceinline__ void cp16(uint32_t s, const float* g) {
    asm volatile("cp.async.cg.shared.global [%0], [%1], 16;" :: "r"(s), "l"(g) : "memory");
}
__device__ __forceinline__ void ldsm4(uint32_t* r, uint32_t addr) {
    asm volatile("ldmatrix.sync.aligned.m8n8.x4.shared.b16 {%0,%1,%2,%3}, [%4];"
                 : "=r"(r[0]), "=r"(r[1]), "=r"(r[2]), "=r"(r[3]) : "r"(addr));
}
__device__ __forceinline__ void mma8(float* c, const uint32_t* a, const uint32_t* b) {
    asm volatile(
        "mma.sync.aligned.m16n8k8.row.col.f32.tf32.tf32.f32 "
        "{%0,%1,%2,%3}, {%4,%5,%6,%7}, {%8,%9}, {%0,%1,%2,%3};"
        : "+f"(c[0]), "+f"(c[1]), "+f"(c[2]), "+f"(c[3])
        : "r"(a[0]), "r"(a[1]), "r"(a[2]), "r"(a[3]), "r"(b[0]), "r"(b[1]));
}
#define CP_COMMIT() asm volatile("cp.async.commit_group;" ::: "memory")
#define CP_WAIT2()  asm volatile("cp.async.wait_group 2;" ::: "memory")

// ---------- prepass: RNA-round f32 -> tf32-valued f32 ----------
__global__ void round_tf32(const float4* __restrict__ in, int which, int n4) {
    float* outp = which == 0 ? g_xr : which == 1 ? g_wr : which == 2 ? g_ar : g_br;
    float4* o4 = (float4*)outp;
    for (int i = blockIdx.x * blockDim.x + threadIdx.x; i < n4; i += gridDim.x * blockDim.x) {
        float4 v = in[i];
        v.x = __uint_as_float(f2tf(v.x));
        v.y = __uint_as_float(f2tf(v.y));
        v.z = __uint_as_float(f2tf(v.z));
        v.w = __uint_as_float(f2tf(v.w));
        o4[i] = v;
    }
}

// ---------- loader: one BK=32 chunk of A[256 rows] + B[128 rows] ----------
template<bool MAIN>
__device__ __forceinline__ void issue_chunk(int kt, uint32_t sbase, int m_block, int n_block, int tid)
{
    const int lrow = tid >> 3;          // 0..31
    const int lg   = tid & 7;           // granule column
    const uint32_t sw = (uint32_t)(lg * 16) ^ (uint32_t)((lrow & 7) << 4);
    const uint32_t sA = sbase + lrow * 128 + sw;
    const uint32_t sB = sbase + A_BYTES + lrow * 128 + sw;

    const float *pa, *pb;
    size_t lda, ldb;
    if (MAIN && kt >= K_TOT / BK) {
        const int kk = (kt - K_TOT / BK) * BK;
        pa = g_xa + (size_t)(m_block + lrow) * RNK + kk + lg * 4;  lda = RNK;
        pb = g_br + (size_t)(n_block + lrow) * RNK + kk + lg * 4;  ldb = RNK;
    } else {
        pa = g_xr + (size_t)(m_block + lrow) * K_TOT + kt * BK + lg * 4;  lda = K_TOT;
        pb = (MAIN ? g_wr : g_ar) + (size_t)(n_block + lrow) * K_TOT + kt * BK + lg * 4;  ldb = K_TOT;
    }
    #pragma unroll
    for (int i = 0; i < 8; i++)
        cp16(sA + i * 32 * 128, pa + (size_t)i * 32 * lda);
    #pragma unroll
    for (int i = 0; i < 4; i++)
        cp16(sB + i * 32 * 128, pb + (size_t)i * 32 * ldb);
    CP_COMMIT();
}

// ---------- GEMM kernel: C[256x128] = A[256,K] * B[128,K]^T (+ epilogue) ----------
// MAIN: A=g_xr|g_xa, B=g_wr|g_br, K=4096+256, out=y (bias add)
// !MAIN: A=g_xr, B=g_ar, K=4096, out=g_xa (scale by d, re-round; device symbol ref)
template<bool MAIN>
__global__ __launch_bounds__(256, 1) void vera_gemm(const float* __restrict__ vec, float* __restrict__ outp)
{
    extern __shared__ char smem[];
    const uint32_t sb = smem_u32(smem);
    const int tid = threadIdx.x;
    const int wid = tid >> 5, lane = tid & 31;
    const int wm = wid >> 1, wn = wid & 1;
    const int m_block = blockIdx.y * BM;
    const int n_block = blockIdx.x * BN;

    const int NCH = MAIN ? (K_TOT / BK + RNK / BK) : (K_TOT / BK);

    float acc[4][8][4];
    #pragma unroll
    for (int i = 0; i < 4; i++)
        #pragma unroll
        for (int j = 0; j < 8; j++)
            #pragma unroll
            for (int k = 0; k < 4; k++) acc[i][j][k] = 0.0f;

    // ldmatrix per-lane constant offsets
    int rowA_off[4];
    #pragma unroll
    for (int mi = 0; mi < 4; mi++)
        rowA_off[mi] = (wm * 64 + mi * 16 + (lane & 15)) * 128;
    const uint32_t gselA = (uint32_t)(lane >> 4);           // 0/1 -> k-halves
    int rowB_off[4];
    #pragma unroll
    for (int njp = 0; njp < 4; njp++)
        rowB_off[njp] = (wn * 64 + njp * 16 + (lane & 7) + ((lane >> 4) << 3)) * 128;
    const uint32_t gselB = (uint32_t)((lane >> 3) & 1);
    const uint32_t xorA = (uint32_t)((lane & 7) << 4);

    // prologue: fill STAGES-1 stages
    #pragma unroll
    for (int s = 0; s < STAGES - 1; s++)
        issue_chunk<MAIN>(s, sb + s * STAGE_BYTES, m_block, n_block, tid);

    for (int kt = 0; kt < NCH; kt++) {
        CP_WAIT2();
        __syncthreads();
        if (kt + STAGES - 1 < NCH)
            issue_chunk<MAIN>(kt + STAGES - 1, sb + ((kt + STAGES - 1) % STAGES) * STAGE_BYTES,
                              m_block, n_block, tid);
        else
            CP_COMMIT();   // keep group accounting aligned

        const uint32_t sA = sb + (kt % STAGES) * STAGE_BYTES;
        const uint32_t sB = sA + A_BYTES;

        #pragma unroll
        for (int k8 = 0; k8 < 4; k8++) {
            const uint32_t koffA = ((uint32_t)(k8 * 32) + gselA * 16) ^ xorA;
            const uint32_t koffB = ((uint32_t)(k8 * 32) + gselB * 16) ^ xorA;
            uint32_t a[4][4], b[4][4];
            #pragma unroll
            for (int mi = 0; mi < 4; mi++)
                ldsm4(a[mi], sA + rowA_off[mi] + koffA);
            #pragma unroll
            for (int njp = 0; njp < 4; njp++)
                ldsm4(b[njp], sB + rowB_off[njp] + koffB);
            #pragma unroll
            for (int mi = 0; mi < 4; mi++)
                #pragma unroll
                for (int nj = 0; nj < 8; nj++)
                    mma8(acc[mi][nj], a[mi], &b[nj >> 1][(nj & 1) * 2]);
        }
    }

    // epilogue
    const int lr = lane >> 2, lc = lane & 3;
    #pragma unroll
    for (int mi = 0; mi < 4; mi++) {
        #pragma unroll
        for (int nj = 0; nj < 8; nj++) {
            const int m = m_block + wm * 64 + mi * 16 + lr;
            const int n = n_block + wn * 64 + nj * 8 + lc * 2;
            if (MAIN) {
                const float b0 = __ldg(&vec[n]), b1 = __ldg(&vec[n + 1]);
                *(float2*)&outp[(size_t)m * N_TOT + n] =
                    make_float2(acc[mi][nj][0] + b0, acc[mi][nj][1] + b1);
                *(float2*)&outp[(size_t)(m + 8) * N_TOT + n] =
                    make_float2(acc[mi][nj][2] + b0, acc[mi][nj][3] + b1);
            } else {
                // Write xa via the DEVICE-side symbol (host cannot pass &g_xa!)
                const float d0 = __ldg(&vec[n]), d1 = __ldg(&vec[n + 1]);
                *(float2*)&g_xa[(size_t)m * RNK + n] = make_float2(
                    __uint_as_float(f2tf(acc[mi][nj][0] * d0)),
                    __uint_as_float(f2tf(acc[mi][nj][1] * d1)));
                *(float2*)&g_xa[(size_t)(m + 8) * RNK + n] = make_float2(
                    __uint_as_float(f2tf(acc[mi][nj][2] * d0)),
                    __uint_as_float(f2tf(acc[mi][nj][3] * d1)));
            }
        }
    }
}

// ---------- launch ----------
extern "C" void kernel_launch(void* const* d_in, const int* in_sizes, int n_in,
                              void* d_out, int out_size)
{
    const float* x    = (const float*)d_in[0];
    const float* W    = (const float*)d_in[1];
    const float* Amat = (const float*)d_in[2];
    const float* Bmat = (const float*)d_in[3];
    const float* dvec = (const float*)d_in[4];
    const float* bias = (const float*)d_in[5];
    float* out = (float*)d_out;

    cudaFuncSetAttribute(vera_gemm<true>,  cudaFuncAttributeMaxDynamicSharedMemorySize, SMEM_TOTAL);
    cudaFuncSetAttribute(vera_gemm<false>, cudaFuncAttributeMaxDynamicSharedMemorySize, SMEM_TOTAL);

    round_tf32<<<1184, 256>>>((const float4*)x,    0, (M_TOT * K_TOT) / 4);
    round_tf32<<<1184, 256>>>((const float4*)W,    1, (N_TOT * K_TOT) / 4);
    round_tf32<<<256,  256>>>((const float4*)Amat, 2, (RNK * K_TOT) / 4);
    round_tf32<<<256,  256>>>((const float4*)Bmat, 3, (N_TOT * RNK) / 4);

    // xa = (x @ A^T) * d  -> g_xa (written device-side)
    vera_gemm<false><<<dim3(RNK / BN, M_TOT / BM), 256, SMEM_TOTAL>>>(dvec, out);
    // y = x @ W^T + xa @ B^T + b
    vera_gemm<true><<<dim3(N_TOT / BN, M_TOT / BM), 256, SMEM_TOTAL>>>(bias, out);
}

// round 6
// speedup vs baseline: 1.4284x; 1.0447x over previous
#include <cuda_runtime.h>
#include <cstdint>
#include <cstddef>

// VeRA: y = x @ W^T + ((x @ A^T) * d) @ B^T + b    (all f32)
// Path: prepass RNA-round to tf32 -> mma.sync m16n8k8 tf32, ldmatrix fragments,
// register double-buffered mainloop.

#define M_TOT 8192
#define N_TOT 4096
#define K_TOT 4096
#define RNK   256

#define BN 128
#define BK 32
#define STAGES 4

// ---------- static scratch ----------
__device__ float g_xr[(size_t)M_TOT * K_TOT];
__device__ float g_wr[(size_t)N_TOT * K_TOT];
__device__ float g_ar[(size_t)RNK * K_TOT];
__device__ float g_br[(size_t)N_TOT * RNK];
__device__ float g_xa[(size_t)M_TOT * RNK];

// ---------- helpers ----------
__device__ __forceinline__ uint32_t f2tf(float f) {
    uint32_t r; asm("cvt.rna.tf32.f32 %0, %1;" : "=r"(r) : "f"(f)); return r;
}
__device__ __forceinline__ uint32_t smem_u32(const void* p) {
    uint32_t a;
    asm("{ .reg .u64 t; cvta.to.shared.u64 t, %1; cvt.u32.u64 %0, t; }" : "=r"(a) : "l"(p));
    return a;
}
__device__ __forceinline__ void cp16(uint32_t s, const float* g) {
    asm volatile("cp.async.cg.shared.global [%0], [%1], 16;" :: "r"(s), "l"(g) : "memory");
}
__device__ __forceinline__ void ldsm4(uint32_t* r, uint32_t addr) {
    asm volatile("ldmatrix.sync.aligned.m8n8.x4.shared.b16 {%0,%1,%2,%3}, [%4];"
                 : "=r"(r[0]), "=r"(r[1]), "=r"(r[2]), "=r"(r[3]) : "r"(addr));
}
__device__ __forceinline__ void mma8(float* c, const uint32_t* a, const uint32_t* b) {
    asm volatile(
        "mma.sync.aligned.m16n8k8.row.col.f32.tf32.tf32.f32 "
        "{%0,%1,%2,%3}, {%4,%5,%6,%7}, {%8,%9}, {%0,%1,%2,%3};"
        : "+f"(c[0]), "+f"(c[1]), "+f"(c[2]), "+f"(c[3])
        : "r"(a[0]), "r"(a[1]), "r"(a[2]), "r"(a[3]), "r"(b[0]), "r"(b[1]));
}
#define CP_COMMIT() asm volatile("cp.async.commit_group;" ::: "memory")
#define CP_WAIT2()  asm volatile("cp.async.wait_group 2;" ::: "memory")

// ---------- prepass ----------
__global__ void round_tf32(const float4* __restrict__ in, int which, int n4) {
    float* outp = which == 0 ? g_xr : which == 1 ? g_wr : which == 2 ? g_ar : g_br;
    float4* o4 = (float4*)outp;
    for (int i = blockIdx.x * blockDim.x + threadIdx.x; i < n4; i += gridDim.x * blockDim.x) {
        float4 v = in[i];
        v.x = __uint_as_float(f2tf(v.x));
        v.y = __uint_as_float(f2tf(v.y));
        v.z = __uint_as_float(f2tf(v.z));
        v.w = __uint_as_float(f2tf(v.w));
        o4[i] = v;
    }
}

// ---------- loader: one BK=32 chunk, A[BM rows] + B[128 rows] ----------
template<bool MAIN, int BM>
__device__ __forceinline__ void issue_chunk(int kt, uint32_t sbase, int m_block, int n_block, int tid)
{
    const int lrow = tid >> 3;
    const int lg   = tid & 7;
    const uint32_t sw = (uint32_t)(lg * 16) ^ (uint32_t)((lrow & 7) << 4);
    const uint32_t sA = sbase + lrow * 128 + sw;
    const uint32_t sB = sbase + BM * 128 + lrow * 128 + sw;

    const float *pa, *pb;
    size_t lda, ldb;
    if (MAIN && kt >= K_TOT / BK) {
        const int kk = (kt - K_TOT / BK) * BK;
        pa = g_xa + (size_t)(m_block + lrow) * RNK + kk + lg * 4;  lda = RNK;
        pb = g_br + (size_t)(n_block + lrow) * RNK + kk + lg * 4;  ldb = RNK;
    } else {
        pa = g_xr + (size_t)(m_block + lrow) * K_TOT + kt * BK + lg * 4;  lda = K_TOT;
        pb = (MAIN ? g_wr : g_ar) + (size_t)(n_block + lrow) * K_TOT + kt * BK + lg * 4;  ldb = K_TOT;
    }
    #pragma unroll
    for (int i = 0; i < BM / 32; i++)
        cp16(sA + i * 32 * 128, pa + (size_t)i * 32 * lda);
    #pragma unroll
    for (int i = 0; i < 4; i++)
        cp16(sB + i * 32 * 128, pb + (size_t)i * 32 * ldb);
    CP_COMMIT();
}

// ---------- GEMM: C[BM x 128] = A[BM,K] * B[128,K]^T, BM = MI*64 ----------
template<bool MAIN, int MI>
__global__ __launch_bounds__(256, 1) void vera_gemm(const float* __restrict__ vec, float* __restrict__ outp)
{
    constexpr int BM = MI * 64;                   // 4 warps along M, MI*16 rows each
    constexpr int A_BYTES = BM * 128;
    constexpr int STAGE_BYTES = (BM + BN) * 128;

    extern __shared__ char smem[];
    const uint32_t sb = smem_u32(smem);
    const int tid = threadIdx.x;
    const int wid = tid >> 5, lane = tid & 31;
    const int wm = wid >> 1, wn = wid & 1;
    const int m_block = blockIdx.y * BM;
    const int n_block = blockIdx.x * BN;

    const int NCH = MAIN ? (K_TOT / BK + RNK / BK) : (K_TOT / BK);

    float acc[MI][8][4];
    #pragma unroll
    for (int i = 0; i < MI; i++)
        #pragma unroll
        for (int j = 0; j < 8; j++)
            #pragma unroll
            for (int k = 0; k < 4; k++) acc[i][j][k] = 0.0f;

    int rowA_off[MI];
    #pragma unroll
    for (int mi = 0; mi < MI; mi++)
        rowA_off[mi] = (wm * (MI * 16) + mi * 16 + (lane & 15)) * 128;
    const uint32_t gselA = (uint32_t)(lane >> 4);
    int rowB_off[4];
    #pragma unroll
    for (int njp = 0; njp < 4; njp++)
        rowB_off[njp] = (wn * 64 + njp * 16 + (lane & 7) + ((lane >> 4) << 3)) * 128;
    const uint32_t gselB = (uint32_t)((lane >> 3) & 1);
    const uint32_t xorA = (uint32_t)((lane & 7) << 4);

    #pragma unroll
    for (int s = 0; s < STAGES - 1; s++)
        issue_chunk<MAIN, BM>(s, sb + s * STAGE_BYTES, m_block, n_block, tid);

    uint32_t af[2][MI][4], bf[2][4][4];

    for (int kt = 0; kt < NCH; kt++) {
        CP_WAIT2();
        __syncthreads();
        if (kt + STAGES - 1 < NCH)
            issue_chunk<MAIN, BM>(kt + STAGES - 1, sb + ((kt + STAGES - 1) % STAGES) * STAGE_BYTES,
                                  m_block, n_block, tid);
        else
            CP_COMMIT();

        const uint32_t sA = sb + (kt % STAGES) * STAGE_BYTES;
        const uint32_t sB = sA + A_BYTES;

        // prime k8=0 fragments
        {
            const uint32_t koffA = (gselA * 16) ^ xorA;
            const uint32_t koffB = (gselB * 16) ^ xorA;
            #pragma unroll
            for (int mi = 0; mi < MI; mi++) ldsm4(af[0][mi], sA + rowA_off[mi] + koffA);
            #pragma unroll
            for (int njp = 0; njp < 4; njp++) ldsm4(bf[0][njp], sB + rowB_off[njp] + koffB);
        }

        #pragma unroll
        for (int k8 = 0; k8 < 4; k8++) {
            const int cur = k8 & 1, nxt = cur ^ 1;
            if (k8 < 3) {
                const uint32_t koffA = ((uint32_t)((k8 + 1) * 32) + gselA * 16) ^ xorA;
                const uint32_t koffB = ((uint32_t)((k8 + 1) * 32) + gselB * 16) ^ xorA;
                #pragma unroll
                for (int mi = 0; mi < MI; mi++) ldsm4(af[nxt][mi], sA + rowA_off[mi] + koffA);
                #pragma unroll
                for (int njp = 0; njp < 4; njp++) ldsm4(bf[nxt][njp], sB + rowB_off[njp] + koffB);
            }
            #pragma unroll
            for (int mi = 0; mi < MI; mi++)
                #pragma unroll
                for (int nj = 0; nj < 8; nj++)
                    mma8(acc[mi][nj], af[cur][mi], &bf[cur][nj >> 1][(nj & 1) * 2]);
        }
    }

    // epilogue
    const int lr = lane >> 2, lc = lane & 3;
    #pragma unroll
    for (int mi = 0; mi < MI; mi++) {
        #pragma unroll
        for (int nj = 0; nj < 8; nj++) {
            const int m = m_block + wm * (MI * 16) + mi * 16 + lr;
            const int n = n_block + wn * 64 + nj * 8 + lc * 2;
            if (MAIN) {
                const float b0 = __ldg(&vec[n]), b1 = __ldg(&vec[n + 1]);
                *(float2*)&outp[(size_t)m * N_TOT + n] =
                    make_float2(acc[mi][nj][0] + b0, acc[mi][nj][1] + b1);
                *(float2*)&outp[(size_t)(m + 8) * N_TOT + n] =
                    make_float2(acc[mi][nj][2] + b0, acc[mi][nj][3] + b1);
            } else {
                const float d0 = __ldg(&vec[n]), d1 = __ldg(&vec[n + 1]);
                *(float2*)&g_xa[(size_t)m * RNK + n] = make_float2(
                    __uint_as_float(f2tf(acc[mi][nj][0] * d0)),
                    __uint_as_float(f2tf(acc[mi][nj][1] * d1)));
                *(float2*)&g_xa[(size_t)(m + 8) * RNK + n] = make_float2(
                    __uint_as_float(f2tf(acc[mi][nj][2] * d0)),
                    __uint_as_float(f2tf(acc[mi][nj][3] * d1)));
            }
        }
    }
}

// ---------- launch ----------
extern "C" void kernel_launch(void* const* d_in, const int* in_sizes, int n_in,
                              void* d_out, int out_size)
{
    const float* x    = (const float*)d_in[0];
    const float* W    = (const float*)d_in[1];
    const float* Amat = (const float*)d_in[2];
    const float* Bmat = (const float*)d_in[3];
    const float* dvec = (const float*)d_in[4];
    const float* bias = (const float*)d_in[5];
    float* out = (float*)d_out;

    constexpr int MAIN_SMEM = STAGES * (256 + BN) * 128;   // 196608
    constexpr int XA_SMEM   = STAGES * (128 + BN) * 128;   // 131072
    cudaFuncSetAttribute(vera_gemm<true, 4>,  cudaFuncAttributeMaxDynamicSharedMemorySize, MAIN_SMEM);
    cudaFuncSetAttribute(vera_gemm<false, 2>, cudaFuncAttributeMaxDynamicSharedMemorySize, XA_SMEM);

    round_tf32<<<2048, 256>>>((const float4*)x,    0, (M_TOT * K_TOT) / 4);
    round_tf32<<<2048, 256>>>((const float4*)W,    1, (N_TOT * K_TOT) / 4);
    round_tf32<<<512,  256>>>((const float4*)Amat, 2, (RNK * K_TOT) / 4);
    round_tf32<<<512,  256>>>((const float4*)Bmat, 3, (N_TOT * RNK) / 4);

    // xa = (x @ A^T) * d  -> g_xa (device-side symbol), BM=128 -> 128 CTAs
    vera_gemm<false, 2><<<dim3(RNK / BN, M_TOT / 128), 256, XA_SMEM>>>(dvec, out);
    // y = x @ W^T + xa @ B^T + b, BM=256 -> 1024 CTAs
    vera_gemm<true, 4><<<dim3(N_TOT / BN, M_TOT / 256), 256, MAIN_SMEM>>>(bias, out);
}

// round 7
// speedup vs baseline: 1.5548x; 1.0885x over previous
#include <cuda_runtime.h>
#include <cstdint>
#include <cstddef>

// VeRA: y = x @ W^T + ((x @ A^T) * d) @ B^T + b    (all f32)
// Path: prepass RNA-round to tf32 -> mma.sync m16n8k8 tf32, ldmatrix fragments,
// continuous cross-chunk register fragment pipeline.

#define M_TOT 8192
#define N_TOT 4096
#define K_TOT 4096
#define RNK   256

#define BN 128
#define BK 32
#define STAGES 4

// ---------- static scratch ----------
__device__ float g_xr[(size_t)M_TOT * K_TOT];
__device__ float g_wr[(size_t)N_TOT * K_TOT];
__device__ float g_ar[(size_t)RNK * K_TOT];
__device__ float g_br[(size_t)N_TOT * RNK];
__device__ float g_xa[(size_t)M_TOT * RNK];

// ---------- helpers ----------
__device__ __forceinline__ uint32_t f2tf(float f) {
    uint32_t r; asm("cvt.rna.tf32.f32 %0, %1;" : "=r"(r) : "f"(f)); return r;
}
__device__ __forceinline__ uint32_t smem_u32(const void* p) {
    uint32_t a;
    asm("{ .reg .u64 t; cvta.to.shared.u64 t, %1; cvt.u32.u64 %0, t; }" : "=r"(a) : "l"(p));
    return a;
}
__device__ __forceinline__ void cp16(uint32_t s, const float* g) {
    asm volatile("cp.async.cg.shared.global [%0], [%1], 16;" :: "r"(s), "l"(g) : "memory");
}
__device__ __forceinline__ void ldsm4(uint32_t* r, uint32_t addr) {
    asm volatile("ldmatrix.sync.aligned.m8n8.x4.shared.b16 {%0,%1,%2,%3}, [%4];"
                 : "=r"(r[0]), "=r"(r[1]), "=r"(r[2]), "=r"(r[3]) : "r"(addr));
}
__device__ __forceinline__ void mma8(float* c, const uint32_t* a, const uint32_t* b) {
    asm volatile(
        "mma.sync.aligned.m16n8k8.row.col.f32.tf32.tf32.f32 "
        "{%0,%1,%2,%3}, {%4,%5,%6,%7}, {%8,%9}, {%0,%1,%2,%3};"
        : "+f"(c[0]), "+f"(c[1]), "+f"(c[2]), "+f"(c[3])
        : "r"(a[0]), "r"(a[1]), "r"(a[2]), "r"(a[3]), "r"(b[0]), "r"(b[1]));
}
#define CP_COMMIT() asm volatile("cp.async.commit_group;" ::: "memory")
#define CP_WAIT(n)  asm volatile("cp.async.wait_group %0;" :: "n"(n) : "memory")

// ---------- prepass ----------
__global__ void round_tf32(const float4* __restrict__ in, int which, int n4) {
    float* outp = which == 0 ? g_xr : which == 1 ? g_wr : which == 2 ? g_ar : g_br;
    float4* o4 = (float4*)outp;
    for (int i = blockIdx.x * blockDim.x + threadIdx.x; i < n4; i += gridDim.x * blockDim.x) {
        float4 v = in[i];
        v.x = __uint_as_float(f2tf(v.x));
        v.y = __uint_as_float(f2tf(v.y));
        v.z = __uint_as_float(f2tf(v.z));
        v.w = __uint_as_float(f2tf(v.w));
        o4[i] = v;
    }
}

// ---------- loader: one BK=32 chunk, A[BM rows] + B[128 rows] ----------
template<bool MAIN, int BM>
__device__ __forceinline__ void issue_chunk(int kt, uint32_t sbase, int m_block, int n_block, int tid)
{
    const int lrow = tid >> 3;
    const int lg   = tid & 7;
    const uint32_t sw = (uint32_t)(lg * 16) ^ (uint32_t)((lrow & 7) << 4);
    const uint32_t sA = sbase + lrow * 128 + sw;
    const uint32_t sB = sbase + BM * 128 + lrow * 128 + sw;

    const float *pa, *pb;
    size_t lda, ldb;
    if (MAIN && kt >= K_TOT / BK) {
        const int kk = (kt - K_TOT / BK) * BK;
        pa = g_xa + (size_t)(m_block + lrow) * RNK + kk + lg * 4;  lda = RNK;
        pb = g_br + (size_t)(n_block + lrow) * RNK + kk + lg * 4;  ldb = RNK;
    } else {
        pa = g_xr + (size_t)(m_block + lrow) * K_TOT + kt * BK + lg * 4;  lda = K_TOT;
        pb = (MAIN ? g_wr : g_ar) + (size_t)(n_block + lrow) * K_TOT + kt * BK + lg * 4;  ldb = K_TOT;
    }
    #pragma unroll
    for (int i = 0; i < BM / 32; i++)
        cp16(sA + i * 32 * 128, pa + (size_t)i * 32 * lda);
    #pragma unroll
    for (int i = 0; i < 4; i++)
        cp16(sB + i * 32 * 128, pb + (size_t)i * 32 * ldb);
    CP_COMMIT();
}

// ---------- GEMM: C[BM x 128] = A[BM,K] * B[128,K]^T, BM = MI*64 ----------
template<bool MAIN, int MI>
__global__ __launch_bounds__(256, 1) void vera_gemm(const float* __restrict__ vec, float* __restrict__ outp)
{
    constexpr int BM = MI * 64;
    constexpr int A_BYTES = BM * 128;
    constexpr int STAGE_BYTES = (BM + BN) * 128;

    extern __shared__ char smem[];
    const uint32_t sb = smem_u32(smem);
    const int tid = threadIdx.x;
    const int wid = tid >> 5, lane = tid & 31;
    const int wm = wid >> 1, wn = wid & 1;
    const int m_block = blockIdx.y * BM;
    const int n_block = blockIdx.x * BN;

    const int NCH = MAIN ? (K_TOT / BK + RNK / BK) : (K_TOT / BK);

    float acc[MI][8][4];
    #pragma unroll
    for (int i = 0; i < MI; i++)
        #pragma unroll
        for (int j = 0; j < 8; j++)
            #pragma unroll
            for (int k = 0; k < 4; k++) acc[i][j][k] = 0.0f;

    int rowA_off[MI];
    #pragma unroll
    for (int mi = 0; mi < MI; mi++)
        rowA_off[mi] = (wm * (MI * 16) + mi * 16 + (lane & 15)) * 128;
    const uint32_t gselA = (uint32_t)(lane >> 4);
    int rowB_off[4];
    #pragma unroll
    for (int njp = 0; njp < 4; njp++)
        rowB_off[njp] = (wn * 64 + njp * 16 + (lane & 7) + ((lane >> 4) << 3)) * 128;
    const uint32_t gselB = (uint32_t)((lane >> 3) & 1);
    const uint32_t xorA = (uint32_t)((lane & 7) << 4);

    // prologue: fill STAGES-1 stages
    #pragma unroll
    for (int s = 0; s < STAGES - 1; s++)
        issue_chunk<MAIN, BM>(s, sb + s * STAGE_BYTES, m_block, n_block, tid);

    uint32_t af[2][MI][4], bf[2][4][4];

    // prime (chunk 0, k8=0)
    CP_WAIT(2);              // chunk 0 (and beyond) arrived
    __syncthreads();
    {
        const uint32_t sA = sb;
        const uint32_t sB = sb + A_BYTES;
        const uint32_t koffA = (gselA * 16) ^ xorA;
        const uint32_t koffB = (gselB * 16) ^ xorA;
        #pragma unroll
        for (int mi = 0; mi < MI; mi++) ldsm4(af[0][mi], sA + rowA_off[mi] + koffA);
        #pragma unroll
        for (int njp = 0; njp < 4; njp++) ldsm4(bf[0][njp], sB + rowB_off[njp] + koffB);
    }

    for (int kt = 0; kt < NCH; kt++) {
        // Guarantee chunks kt AND kt+1 have arrived (prefetch at k8=3 reads kt+1's stage).
        CP_WAIT(1);
        __syncthreads();     // releases stage (kt-1)%4 for the issue below
        if (kt + STAGES - 1 < NCH)
            issue_chunk<MAIN, BM>(kt + STAGES - 1, sb + ((kt + STAGES - 1) % STAGES) * STAGE_BYTES,
                                  m_block, n_block, tid);
        else
            CP_COMMIT();     // keep group accounting aligned

        const uint32_t sA = sb + (kt % STAGES) * STAGE_BYTES;
        const uint32_t sB = sA + A_BYTES;
        const uint32_t sA1 = sb + ((kt + 1) % STAGES) * STAGE_BYTES;
        const uint32_t sB1 = sA1 + A_BYTES;

        #pragma unroll
        for (int k8 = 0; k8 < 4; k8++) {
            const int cur = k8 & 1, nxt = cur ^ 1;
            if (k8 < 3) {
                const uint32_t koffA = ((uint32_t)((k8 + 1) * 32) + gselA * 16) ^ xorA;
                const uint32_t koffB = ((uint32_t)((k8 + 1) * 32) + gselB * 16) ^ xorA;
                #pragma unroll
                for (int mi = 0; mi < MI; mi++) ldsm4(af[nxt][mi], sA + rowA_off[mi] + koffA);
                #pragma unroll
                for (int njp = 0; njp < 4; njp++) ldsm4(bf[nxt][njp], sB + rowB_off[njp] + koffB);
            } else if (kt + 1 < NCH) {
                // cross-chunk prefetch: (kt+1, k8=0) from the next stage
                const uint32_t koffA = (gselA * 16) ^ xorA;
                const uint32_t koffB = (gselB * 16) ^ xorA;
                #pragma unroll
                for (int mi = 0; mi < MI; mi++) ldsm4(af[nxt][mi], sA1 + rowA_off[mi] + koffA);
                #pragma unroll
                for (int njp = 0; njp < 4; njp++) ldsm4(bf[nxt][njp], sB1 + rowB_off[njp] + koffB);
            }
            #pragma unroll
            for (int mi = 0; mi < MI; mi++)
                #pragma unroll
                for (int nj = 0; nj < 8; nj++)
                    mma8(acc[mi][nj], af[cur][mi], &bf[cur][nj >> 1][(nj & 1) * 2]);
        }
    }

    // epilogue
    const int lr = lane >> 2, lc = lane & 3;
    #pragma unroll
    for (int mi = 0; mi < MI; mi++) {
        #pragma unroll
        for (int nj = 0; nj < 8; nj++) {
            const int m = m_block + wm * (MI * 16) + mi * 16 + lr;
            const int n = n_block + wn * 64 + nj * 8 + lc * 2;
            if (MAIN) {
                const float b0 = __ldg(&vec[n]), b1 = __ldg(&vec[n + 1]);
                *(float2*)&outp[(size_t)m * N_TOT + n] =
                    make_float2(acc[mi][nj][0] + b0, acc[mi][nj][1] + b1);
                *(float2*)&outp[(size_t)(m + 8) * N_TOT + n] =
                    make_float2(acc[mi][nj][2] + b0, acc[mi][nj][3] + b1);
            } else {
                const float d0 = __ldg(&vec[n]), d1 = __ldg(&vec[n + 1]);
                *(float2*)&g_xa[(size_t)m * RNK + n] = make_float2(
                    __uint_as_float(f2tf(acc[mi][nj][0] * d0)),
                    __uint_as_float(f2tf(acc[mi][nj][1] * d1)));
                *(float2*)&g_xa[(size_t)(m + 8) * RNK + n] = make_float2(
                    __uint_as_float(f2tf(acc[mi][nj][2] * d0)),
                    __uint_as_float(f2tf(acc[mi][nj][3] * d1)));
            }
        }
    }
}

// ---------- launch ----------
extern "C" void kernel_launch(void* const* d_in, const int* in_sizes, int n_in,
                              void* d_out, int out_size)
{
    const float* x    = (const float*)d_in[0];
    const float* W    = (const float*)d_in[1];
    const float* Amat = (const float*)d_in[2];
    const float* Bmat = (const float*)d_in[3];
    const float* dvec = (const float*)d_in[4];
    const float* bias = (const float*)d_in[5];
    float* out = (float*)d_out;

    constexpr int MAIN_SMEM = STAGES * (256 + BN) * 128;   // 196608
    constexpr int XA_SMEM   = STAGES * (128 + BN) * 128;   // 131072
    cudaFuncSetAttribute(vera_gemm<true, 4>,  cudaFuncAttributeMaxDynamicSharedMemorySize, MAIN_SMEM);
    cudaFuncSetAttribute(vera_gemm<false, 2>, cudaFuncAttributeMaxDynamicSharedMemorySize, XA_SMEM);

    round_tf32<<<2048, 256>>>((const float4*)x,    0, (M_TOT * K_TOT) / 4);
    round_tf32<<<2048, 256>>>((const float4*)W,    1, (N_TOT * K_TOT) / 4);
    round_tf32<<<512,  256>>>((const float4*)Amat, 2, (RNK * K_TOT) / 4);
    round_tf32<<<512,  256>>>((const float4*)Bmat, 3, (N_TOT * RNK) / 4);

    vera_gemm<false, 2><<<dim3(RNK / BN, M_TOT / 128), 256, XA_SMEM>>>(dvec, out);
    vera_gemm<true, 4><<<dim3(N_TOT / BN, M_TOT / 256), 256, MAIN_SMEM>>>(bias, out);
}

// round 8
// speedup vs baseline: 1.5610x; 1.0040x over previous
#include <cuda_runtime.h>
#include <cstdint>
#include <cstddef>

// VeRA: y = x @ W^T + ((x @ A^T) * d) @ B^T + b    (all f32)
// Path: fused RNA-round prepass -> mma.sync m16n8k8 tf32, ldmatrix fragments,
// continuous cross-chunk register fragment pipeline, GROUP_M rasterization.

#define M_TOT 8192
#define N_TOT 4096
#define K_TOT 4096
#define RNK   256

#define BN 128
#define BK 32
#define STAGES 4
#define GROUP_M 8

// ---------- static scratch ----------
__device__ float g_xr[(size_t)M_TOT * K_TOT];
__device__ float g_wr[(size_t)N_TOT * K_TOT];
__device__ float g_ar[(size_t)RNK * K_TOT];
__device__ float g_br[(size_t)N_TOT * RNK];
__device__ float g_xa[(size_t)M_TOT * RNK];

// ---------- helpers ----------
__device__ __forceinline__ uint32_t f2tf(float f) {
    uint32_t r; asm("cvt.rna.tf32.f32 %0, %1;" : "=r"(r) : "f"(f)); return r;
}
__device__ __forceinline__ uint32_t smem_u32(const void* p) {
    uint32_t a;
    asm("{ .reg .u64 t; cvta.to.shared.u64 t, %1; cvt.u32.u64 %0, t; }" : "=r"(a) : "l"(p));
    return a;
}
__device__ __forceinline__ void cp16(uint32_t s, const float* g) {
    asm volatile("cp.async.cg.shared.global [%0], [%1], 16;" :: "r"(s), "l"(g) : "memory");
}
__device__ __forceinline__ void ldsm4(uint32_t* r, uint32_t addr) {
    asm volatile("ldmatrix.sync.aligned.m8n8.x4.shared.b16 {%0,%1,%2,%3}, [%4];"
                 : "=r"(r[0]), "=r"(r[1]), "=r"(r[2]), "=r"(r[3]) : "r"(addr));
}
__device__ __forceinline__ void mma8(float* c, const uint32_t* a, const uint32_t* b) {
    asm volatile(
        "mma.sync.aligned.m16n8k8.row.col.f32.tf32.tf32.f32 "
        "{%0,%1,%2,%3}, {%4,%5,%6,%7}, {%8,%9}, {%0,%1,%2,%3};"
        : "+f"(c[0]), "+f"(c[1]), "+f"(c[2]), "+f"(c[3])
        : "r"(a[0]), "r"(a[1]), "r"(a[2]), "r"(a[3]), "r"(b[0]), "r"(b[1]));
}
#define CP_COMMIT() asm volatile("cp.async.commit_group;" ::: "memory")
#define CP_WAIT(n)  asm volatile("cp.async.wait_group %0;" :: "n"(n) : "memory")

// ---------- fused prepass: RNA-round x, W, A, B in one launch ----------
__global__ void round_all(const float4* __restrict__ x, const float4* __restrict__ W,
                          const float4* __restrict__ A, const float4* __restrict__ B)
{
    const int n_x = (M_TOT * K_TOT) / 4;
    const int n_w = (N_TOT * K_TOT) / 4;
    const int n_a = (RNK * K_TOT) / 4;
    const int n_b = (N_TOT * RNK) / 4;
    const int total = n_x + n_w + n_a + n_b;
    for (int i = blockIdx.x * blockDim.x + threadIdx.x; i < total; i += gridDim.x * blockDim.x) {
        const float4* src; float4* dst; int j = i;
        if (j < n_x)              { src = x; dst = (float4*)g_xr; }
        else if ((j -= n_x) < n_w){ src = W; dst = (float4*)g_wr; }
        else if ((j -= n_w) < n_a){ src = A; dst = (float4*)g_ar; }
        else                      { j -= n_a; src = B; dst = (float4*)g_br; }
        float4 v = src[j];
        v.x = __uint_as_float(f2tf(v.x));
        v.y = __uint_as_float(f2tf(v.y));
        v.z = __uint_as_float(f2tf(v.z));
        v.w = __uint_as_float(f2tf(v.w));
        dst[j] = v;
    }
}

// ---------- loader: one BK=32 chunk, A[BM rows] + B[128 rows] ----------
template<bool MAIN, int BM>
__device__ __forceinline__ void issue_chunk(int kt, uint32_t sbase, int m_block, int n_block, int tid)
{
    const int lrow = tid >> 3;
    const int lg   = tid & 7;
    const uint32_t sw = (uint32_t)(lg * 16) ^ (uint32_t)((lrow & 7) << 4);
    const uint32_t sA = sbase + lrow * 128 + sw;
    const uint32_t sB = sbase + BM * 128 + lrow * 128 + sw;

    const float *pa, *pb;
    size_t lda, ldb;
    if (MAIN && kt >= K_TOT / BK) {
        const int kk = (kt - K_TOT / BK) * BK;
        pa = g_xa + (size_t)(m_block + lrow) * RNK + kk + lg * 4;  lda = RNK;
        pb = g_br + (size_t)(n_block + lrow) * RNK + kk + lg * 4;  ldb = RNK;
    } else {
        pa = g_xr + (size_t)(m_block + lrow) * K_TOT + kt * BK + lg * 4;  lda = K_TOT;
        pb = (MAIN ? g_wr : g_ar) + (size_t)(n_block + lrow) * K_TOT + kt * BK + lg * 4;  ldb = K_TOT;
    }
    #pragma unroll
    for (int i = 0; i < BM / 32; i++)
        cp16(sA + i * 32 * 128, pa + (size_t)i * 32 * lda);
    #pragma unroll
    for (int i = 0; i < 4; i++)
        cp16(sB + i * 32 * 128, pb + (size_t)i * 32 * ldb);
    CP_COMMIT();
}

// ---------- GEMM: C[BM x 128] = A[BM,K] * B[128,K]^T, BM = MI*64 ----------
template<bool MAIN, int MI>
__global__ __launch_bounds__(256, 1) void vera_gemm(const float* __restrict__ vec, float* __restrict__ outp)
{
    constexpr int BM = MI * 64;
    constexpr int A_BYTES = BM * 128;
    constexpr int STAGE_BYTES = (BM + BN) * 128;

    extern __shared__ char smem[];
    const uint32_t sb = smem_u32(smem);
    const int tid = threadIdx.x;
    const int wid = tid >> 5, lane = tid & 31;
    const int wm = wid >> 1, wn = wid & 1;

    // GROUP_M rasterization: wave-concurrent CTAs cover GROUP_M m-blocks x many n-blocks
    const int nbx = gridDim.x;                       // #n blocks
    const int id = blockIdx.y * nbx + blockIdx.x;
    const int per_group = GROUP_M * nbx;
    const int grp = id / per_group;
    const int rem = id % per_group;
    const int m_idx = grp * GROUP_M + (rem % GROUP_M);
    const int n_idx = rem / GROUP_M;
    const int m_block = m_idx * BM;
    const int n_block = n_idx * BN;

    const int NCH = MAIN ? (K_TOT / BK + RNK / BK) : (K_TOT / BK);

    float acc[MI][8][4];
    #pragma unroll
    for (int i = 0; i < MI; i++)
        #pragma unroll
        for (int j = 0; j < 8; j++)
            #pragma unroll
            for (int k = 0; k < 4; k++) acc[i][j][k] = 0.0f;

    int rowA_off[MI];
    #pragma unroll
    for (int mi = 0; mi < MI; mi++)
        rowA_off[mi] = (wm * (MI * 16) + mi * 16 + (lane & 15)) * 128;
    const uint32_t gselA = (uint32_t)(lane >> 4);
    int rowB_off[4];
    #pragma unroll
    for (int njp = 0; njp < 4; njp++)
        rowB_off[njp] = (wn * 64 + njp * 16 + (lane & 7) + ((lane >> 4) << 3)) * 128;
    const uint32_t gselB = (uint32_t)((lane >> 3) & 1);
    const uint32_t xorA = (uint32_t)((lane & 7) << 4);

    // prologue: fill STAGES-1 stages
    #pragma unroll
    for (int s = 0; s < STAGES - 1; s++)
        issue_chunk<MAIN, BM>(s, sb + s * STAGE_BYTES, m_block, n_block, tid);

    uint32_t af[2][MI][4], bf[2][4][4];

    // prime (chunk 0, k8=0)
    CP_WAIT(2);
    __syncthreads();
    {
        const uint32_t sA = sb;
        const uint32_t sB = sb + A_BYTES;
        const uint32_t koffA = (gselA * 16) ^ xorA;
        const uint32_t koffB = (gselB * 16) ^ xorA;
        #pragma unroll
        for (int mi = 0; mi < MI; mi++) ldsm4(af[0][mi], sA + rowA_off[mi] + koffA);
        #pragma unroll
        for (int njp = 0; njp < 4; njp++) ldsm4(bf[0][njp], sB + rowB_off[njp] + koffB);
    }

    for (int kt = 0; kt < NCH; kt++) {
        CP_WAIT(1);          // chunks kt and kt+1 resident
        __syncthreads();     // releases stage (kt-1)%4
        if (kt + STAGES - 1 < NCH)
            issue_chunk<MAIN, BM>(kt + STAGES - 1, sb + ((kt + STAGES - 1) % STAGES) * STAGE_BYTES,
                                  m_block, n_block, tid);
        else
            CP_COMMIT();

        const uint32_t sA = sb + (kt % STAGES) * STAGE_BYTES;
        const uint32_t sB = sA + A_BYTES;
        const uint32_t sA1 = sb + ((kt + 1) % STAGES) * STAGE_BYTES;
        const uint32_t sB1 = sA1 + A_BYTES;

        #pragma unroll
        for (int k8 = 0; k8 < 4; k8++) {
            const int cur = k8 & 1, nxt = cur ^ 1;
            if (k8 < 3) {
                const uint32_t koffA = ((uint32_t)((k8 + 1) * 32) + gselA * 16) ^ xorA;
                const uint32_t koffB = ((uint32_t)((k8 + 1) * 32) + gselB * 16) ^ xorA;
                #pragma unroll
                for (int mi = 0; mi < MI; mi++) ldsm4(af[nxt][mi], sA + rowA_off[mi] + koffA);
                #pragma unroll
                for (int njp = 0; njp < 4; njp++) ldsm4(bf[nxt][njp], sB + rowB_off[njp] + koffB);
            } else if (kt + 1 < NCH) {
                const uint32_t koffA = (gselA * 16) ^ xorA;
                const uint32_t koffB = (gselB * 16) ^ xorA;
                #pragma unroll
                for (int mi = 0; mi < MI; mi++) ldsm4(af[nxt][mi], sA1 + rowA_off[mi] + koffA);
                #pragma unroll
                for (int njp = 0; njp < 4; njp++) ldsm4(bf[nxt][njp], sB1 + rowB_off[njp] + koffB);
            }
            #pragma unroll
            for (int mi = 0; mi < MI; mi++)
                #pragma unroll
                for (int nj = 0; nj < 8; nj++)
                    mma8(acc[mi][nj], af[cur][mi], &bf[cur][nj >> 1][(nj & 1) * 2]);
        }
    }

    // epilogue
    const int lr = lane >> 2, lc = lane & 3;
    #pragma unroll
    for (int mi = 0; mi < MI; mi++) {
        #pragma unroll
        for (int nj = 0; nj < 8; nj++) {
            const int m = m_block + wm * (MI * 16) + mi * 16 + lr;
            const int n = n_block + wn * 64 + nj * 8 + lc * 2;
            if (MAIN) {
                const float b0 = __ldg(&vec[n]), b1 = __ldg(&vec[n + 1]);
                *(float2*)&outp[(size_t)m * N_TOT + n] =
                    make_float2(acc[mi][nj][0] + b0, acc[mi][nj][1] + b1);
                *(float2*)&outp[(size_t)(m + 8) * N_TOT + n] =
                    make_float2(acc[mi][nj][2] + b0, acc[mi][nj][3] + b1);
            } else {
                const float d0 = __ldg(&vec[n]), d1 = __ldg(&vec[n + 1]);
                *(float2*)&g_xa[(size_t)m * RNK + n] = make_float2(
                    __uint_as_float(f2tf(acc[mi][nj][0] * d0)),
                    __uint_as_float(f2tf(acc[mi][nj][1] * d1)));
                *(float2*)&g_xa[(size_t)(m + 8) * RNK + n] = make_float2(
                    __uint_as_float(f2tf(acc[mi][nj][2] * d0)),
                    __uint_as_float(f2tf(acc[mi][nj][3] * d1)));
            }
        }
    }
}

// ---------- launch ----------
extern "C" void kernel_launch(void* const* d_in, const int* in_sizes, int n_in,
                              void* d_out, int out_size)
{
    const float* x    = (const float*)d_in[0];
    const float* W    = (const float*)d_in[1];
    const float* Amat = (const float*)d_in[2];
    const float* Bmat = (const float*)d_in[3];
    const float* dvec = (const float*)d_in[4];
    const float* bias = (const float*)d_in[5];
    float* out = (float*)d_out;

    constexpr int MAIN_SMEM = STAGES * (256 + BN) * 128;   // 196608
    constexpr int XA_SMEM   = STAGES * (128 + BN) * 128;   // 131072
    cudaFuncSetAttribute(vera_gemm<true, 4>,  cudaFuncAttributeMaxDynamicSharedMemorySize, MAIN_SMEM);
    cudaFuncSetAttribute(vera_gemm<false, 2>, cudaFuncAttributeMaxDynamicSharedMemorySize, XA_SMEM);

    // 1 launch: round x, W, A, B to tf32 (RNA)
    round_all<<<3552, 256>>>((const float4*)x, (const float4*)W,
                             (const float4*)Amat, (const float4*)Bmat);

    // xa = (x @ A^T) * d  -> g_xa (device-side symbol)
    vera_gemm<false, 2><<<dim3(RNK / BN, M_TOT / 128), 256, XA_SMEM>>>(dvec, out);
    // y = x @ W^T + xa @ B^T + b
    vera_gemm<true, 4><<<dim3(N_TOT / BN, M_TOT / 256), 256, MAIN_SMEM>>>(bias, out);
}